// round 16
// baseline (speedup 1.0000x reference)
#include <cuda_runtime.h>
#include <cuda_fp16.h>
#include <mma.h>

using namespace nvcuda;

#define IN_F   4096
#define OUT_F  4096
#define RANK   64
#define M_ROWS 8192

__device__ __half g_win [RANK * IN_F];        // [64][4096] f16
__device__ __half g_wout[OUT_F * RANK];       // [4096][64] f16
__device__ __half g_xp  [M_ROWS * RANK];      // [8192][64] f16
__device__ float  g_xp32[2 * M_ROWS * RANK];  // K-split partials, f32

// ---------------------------------------------------------------------------
// helpers
// ---------------------------------------------------------------------------
__device__ __forceinline__ void cp_async16(void* smem_dst, const void* gsrc) {
    unsigned s = (unsigned)__cvta_generic_to_shared(smem_dst);
    asm volatile("cp.async.cg.shared.global [%0], [%1], 16;\n" :: "r"(s), "l"(gsrc));
}
__device__ __forceinline__ void cp_async_commit() {
    asm volatile("cp.async.commit_group;\n");
}
template <int N>
__device__ __forceinline__ void cp_async_wait() {
    asm volatile("cp.async.wait_group %0;\n" :: "n"(N));
}

__device__ __forceinline__ void soft_threshold4(float4 w, float s,
                                                float& o0, float& o1, float& o2, float& o3) {
    float m0 = fabsf(w.x), m1 = fabsf(w.y), m2 = fabsf(w.z), m3 = fabsf(w.w);
    float lo01 = fminf(m0, m1), hi01 = fmaxf(m0, m1);
    float lo23 = fminf(m2, m3), hi23 = fmaxf(m2, m3);
    float t = fminf(fmaxf(lo01, lo23), fminf(hi01, hi23));  // 2nd-smallest
    o0 = copysignf(fmaxf(m0 - t, 0.0f), w.x) * s;
    o1 = copysignf(fmaxf(m1 - t, 0.0f), w.y) * s;
    o2 = copysignf(fmaxf(m2 - t, 0.0f), w.z) * s;
    o3 = copysignf(fmaxf(m3 - t, 0.0f), w.w) * s;
}

// ---------------------------------------------------------------------------
// Weight prep: threshold+scale -> g_win, g_wout
// ---------------------------------------------------------------------------
__global__ void prep_weights_kernel(const float* __restrict__ win,
                                    const float* __restrict__ wout,
                                    const float* __restrict__ scale_in,
                                    const float* __restrict__ scale_out) {
    const int NGI = RANK * IN_F / 4;    // 65536
    const int NGO = OUT_F * RANK / 4;   // 65536
    int idx = blockIdx.x * blockDim.x + threadIdx.x;
    if (idx < NGI) {
        float4 w = reinterpret_cast<const float4*>(win)[idx];
        float o0, o1, o2, o3;
        soft_threshold4(w, __ldg(scale_in), o0, o1, o2, o3);
        __half2* dst = reinterpret_cast<__half2*>(g_win) + idx * 2;
        dst[0] = __floats2half2_rn(o0, o1);
        dst[1] = __floats2half2_rn(o2, o3);
    } else if (idx < NGI + NGO) {
        int j = idx - NGI;
        float4 w = reinterpret_cast<const float4*>(wout)[j];
        float o0, o1, o2, o3;
        soft_threshold4(w, __ldg(scale_out), o0, o1, o2, o3);
        __half2* dst = reinterpret_cast<__half2*>(g_wout) + j * 2;
        dst[0] = __floats2half2_rn(o0, o1);
        dst[1] = __floats2half2_rn(o2, o3);
    }
}

// ---------------------------------------------------------------------------
// GEMM1 (K-split x2): xp32[ks][m,r] = sum_{k in half ks} f16(x[m,k])*g_win[r,k]
// BM=64, BK=64, grid (128, 2). Now 3 CTAs/SM (launch_bounds 256,3) for more
// in-flight DRAM reads. Double-buffered smem, 2-deep register prefetch.
// ---------------------------------------------------------------------------
#define G1_LDA 72   // half, padded

__global__ __launch_bounds__(256, 3)
void gemm1_kernel(const float* __restrict__ x) {
    extern __shared__ __half sm1[];
    __half* A0 = sm1;                   // [64][72]
    __half* A1 = sm1 + 64 * G1_LDA;
    __half* B0 = sm1 + 2 * 64 * G1_LDA;
    __half* B1 = sm1 + 3 * 64 * G1_LDA;

    const int tid  = threadIdx.x;
    const int warp = tid >> 5;
    const int wm   = warp & 3;   // 16 rows
    const int wn   = warp >> 2;  // 32 cols
    const int m0   = blockIdx.x * 64;
    const int ks   = blockIdx.y;
    const int k0   = ks * (IN_F / 2);

    wmma::fragment<wmma::accumulator, 16, 16, 16, float> acc[2];
    wmma::fill_fragment(acc[0], 0.0f);
    wmma::fill_fragment(acc[1], 0.0f);

    const int NK = (IN_F / 2) / 64;  // 32

    float4 xa0[4], xa1[4];
    int4   wb0[2], wb1[2];

    auto ldx = [&](float4* xa, int kt) {
        #pragma unroll
        for (int it = 0; it < 4; it++) {
            int i = tid + it * 256;
            int row = i >> 4, c4 = i & 15;
            xa[it] = __ldcs(reinterpret_cast<const float4*>(
                &x[(size_t)(m0 + row) * IN_F + k0 + kt * 64 + c4 * 4]));
        }
    };
    auto ldw = [&](int4* wb, int kt) {
        #pragma unroll
        for (int it = 0; it < 2; it++) {
            int i = tid + it * 256;
            int row = i >> 3, c8 = i & 7;
            wb[it] = *reinterpret_cast<const int4*>(
                &g_win[row * IN_F + k0 + kt * 64 + c8 * 8]);
        }
    };
    auto stage = [&](__half* A, __half* B, const float4* xa, const int4* wb) {
        #pragma unroll
        for (int it = 0; it < 4; it++) {
            int i = tid + it * 256;
            int row = i >> 4, c4 = i & 15;
            __half* p = &A[row * G1_LDA + c4 * 4];
            reinterpret_cast<__half2*>(p)[0] = __floats2half2_rn(xa[it].x, xa[it].y);
            reinterpret_cast<__half2*>(p)[1] = __floats2half2_rn(xa[it].z, xa[it].w);
        }
        #pragma unroll
        for (int it = 0; it < 2; it++) {
            int i = tid + it * 256;
            int row = i >> 3, c8 = i & 7;
            *reinterpret_cast<int4*>(&B[row * G1_LDA + c8 * 8]) = wb[it];
        }
    };
    auto mma = [&](const __half* A, const __half* B) {
        #pragma unroll
        for (int k4 = 0; k4 < 4; k4++) {
            wmma::fragment<wmma::matrix_a, 16, 16, 16, __half, wmma::row_major> a;
            wmma::load_matrix_sync(a, &A[(wm * 16) * G1_LDA + k4 * 16], G1_LDA);
            #pragma unroll
            for (int j = 0; j < 2; j++) {
                wmma::fragment<wmma::matrix_b, 16, 16, 16, __half, wmma::col_major> b;
                wmma::load_matrix_sync(b, &B[(wn * 32 + j * 16) * G1_LDA + k4 * 16], G1_LDA);
                wmma::mma_sync(acc[j], a, b, acc[j]);
            }
        }
    };

    ldx(xa0, 0); ldw(wb0, 0);
    ldx(xa1, 1); ldw(wb1, 1);

    for (int kt = 0; kt < NK; kt += 2) {
        stage(A0, B0, xa0, wb0);
        __syncthreads();
        if (kt + 2 < NK) { ldx(xa0, kt + 2); ldw(wb0, kt + 2); }
        mma(A0, B0);

        stage(A1, B1, xa1, wb1);
        __syncthreads();
        if (kt + 3 < NK) { ldx(xa1, kt + 3); ldw(wb1, kt + 3); }
        mma(A1, B1);
    }

    float* outp = g_xp32 + (size_t)ks * M_ROWS * RANK;
    #pragma unroll
    for (int j = 0; j < 2; j++)
        wmma::store_matrix_sync(&outp[(size_t)(m0 + wm * 16) * RANK + wn * 32 + j * 16],
                                acc[j], RANK, wmma::mem_row_major);
}

// ---------------------------------------------------------------------------
// Combine: g_xp[m][c] = f16(xp32[0][m][c] + xp32[1][m][c])  ([8192][64])
// float4-wide: each thread combines 4 floats from each half.
// ---------------------------------------------------------------------------
__global__ void combine_xp_kernel() {
    int i = blockIdx.x * blockDim.x + threadIdx.x;   // over 8192*16 float4
    if (i >= M_ROWS * (RANK / 4)) return;
    float4 a = __ldcg(reinterpret_cast<const float4*>(g_xp32) + i);
    float4 b = __ldcg(reinterpret_cast<const float4*>(g_xp32 + (size_t)M_ROWS * RANK) + i);
    __half2 h0 = __floats2half2_rn(a.x + b.x, a.y + b.y);
    __half2 h1 = __floats2half2_rn(a.z + b.z, a.w + b.w);
    reinterpret_cast<__half2*>(g_xp)[i * 2]     = h0;
    reinterpret_cast<__half2*>(g_xp)[i * 2 + 1] = h1;
}

// ---------------------------------------------------------------------------
// GEMM2: out[m,o] = (xp[m,:] . wout[o,:] + bias[o]) / 64   (K=64)
// BM=128, BN=128. Bias via single-row smem + ldm=0 broadcast fragment load.
// Direct store_matrix_sync epilogue. (round-14/15 exact — best measured)
// ---------------------------------------------------------------------------
#define G2_LD 72    // half, padded (K=64)

__global__ __launch_bounds__(256, 2)
void gemm2_kernel(const float* __restrict__ bias, float* __restrict__ out) {
    extern __shared__ __half sm2[];
    __half* Ps = sm2;                 // [128][72]  18432 B
    __half* Ws = sm2 + 128 * G2_LD;   // [128][72]  18432 B
    float* bias_row = reinterpret_cast<float*>(sm2 + 2 * 128 * G2_LD);  // [128] 512 B

    const int tid  = threadIdx.x;
    const int warp = tid >> 5;
    const int wm   = warp & 3;   // 32 rows
    const int wn   = warp >> 2;  // 64 cols
    const int m0   = blockIdx.x * 128;
    const int n0   = blockIdx.y * 128;

    #pragma unroll
    for (int it = 0; it < 4; it++) {
        int c = tid + it * 256;
        int row = c >> 3, off = c & 7;
        cp_async16(Ps + row * G2_LD + off * 8,
                   g_xp + (size_t)(m0 + row) * RANK + off * 8);
    }
    #pragma unroll
    for (int it = 0; it < 4; it++) {
        int c = tid + it * 256;
        int row = c >> 3, off = c & 7;
        cp_async16(Ws + row * G2_LD + off * 8,
                   g_wout + (size_t)(n0 + row) * RANK + off * 8);
    }
    cp_async_commit();

    if (tid < 128) bias_row[tid] = __ldg(&bias[n0 + tid]);

    cp_async_wait<0>();
    __syncthreads();

    wmma::fragment<wmma::accumulator, 16, 16, 16, float> acc[2][4];
    #pragma unroll
    for (int i = 0; i < 2; i++)
        #pragma unroll
        for (int j = 0; j < 4; j++) wmma::fill_fragment(acc[i][j], 0.0f);

    #pragma unroll
    for (int k4 = 0; k4 < 4; k4++) {   // K = 64
        wmma::fragment<wmma::matrix_a, 16, 16, 16, __half, wmma::row_major> a[2];
        #pragma unroll
        for (int i = 0; i < 2; i++)
            wmma::load_matrix_sync(a[i], &Ps[(wm * 32 + i * 16) * G2_LD + k4 * 16], G2_LD);
        #pragma unroll
        for (int j = 0; j < 4; j++) {
            wmma::fragment<wmma::matrix_b, 16, 16, 16, __half, wmma::col_major> b;
            wmma::load_matrix_sync(b, &Ws[(wn * 64 + j * 16) * G2_LD + k4 * 16], G2_LD);
            #pragma unroll
            for (int i = 0; i < 2; i++)
                wmma::mma_sync(acc[i][j], a[i], b, acc[i][j]);
        }
    }

    const float scaling = 1.0f / (float)RANK;
    #pragma unroll
    for (int i = 0; i < 2; i++)
        #pragma unroll
        for (int j = 0; j < 4; j++) {
            // ldm=0: every fragment row aliases the same 64B bias row;
            // value depends only on column -> layout-independent.
            wmma::fragment<wmma::accumulator, 16, 16, 16, float> bf;
            wmma::load_matrix_sync(bf, &bias_row[wn * 64 + j * 16], 0,
                                   wmma::mem_row_major);
            #pragma unroll
            for (int e = 0; e < acc[i][j].num_elements; e++)
                acc[i][j].x[e] = (acc[i][j].x[e] + bf.x[e]) * scaling;
            wmma::store_matrix_sync(
                &out[(size_t)(m0 + wm * 32 + i * 16) * OUT_F + n0 + wn * 64 + j * 16],
                acc[i][j], OUT_F, wmma::mem_row_major);
        }
}

// ---------------------------------------------------------------------------
// Launcher
// ---------------------------------------------------------------------------
extern "C" void kernel_launch(void* const* d_in, const int* in_sizes, int n_in,
                              void* d_out, int out_size) {
    const float* x         = (const float*)d_in[0];
    const float* weight_in = (const float*)d_in[1];
    const float* weight_out= (const float*)d_in[2];
    const float* bias      = (const float*)d_in[3];
    const float* scale_in  = (const float*)d_in[4];
    const float* scale_out = (const float*)d_in[5];
    float* out = (float*)d_out;

    const int M = in_sizes[0] / IN_F;  // 8192

    {
        int total = RANK * IN_F / 4 + OUT_F * RANK / 4;   // 131072
        prep_weights_kernel<<<(total + 255) / 256, 256>>>(
            weight_in, weight_out, scale_in, scale_out);
    }
    {
        size_t smem = 4 * (size_t)64 * G1_LDA * sizeof(__half);  // 36864
        dim3 grid(M / 64, 2);
        gemm1_kernel<<<grid, 256, smem>>>(x);
    }
    {
        int total = M_ROWS * (RANK / 4);  // 131072
        combine_xp_kernel<<<(total + 255) / 256, 256>>>();
    }
    {
        size_t smem = 2 * (size_t)128 * G2_LD * sizeof(__half) + 512;  // 37376
        dim3 grid(M / 128, OUT_F / 128);
        gemm2_kernel<<<grid, 256, smem>>>(bias, out);
    }
}

// round 17
// speedup vs baseline: 1.3720x; 1.3720x over previous
#include <cuda_runtime.h>
#include <cuda_fp16.h>
#include <mma.h>

using namespace nvcuda;

#define IN_F   4096
#define OUT_F  4096
#define RANK   64
#define M_ROWS 8192

__device__ __half g_win [RANK * IN_F];        // [64][4096] f16
__device__ __half g_wout[OUT_F * RANK];       // [4096][64] f16
__device__ __half g_xp  [M_ROWS * RANK];      // [8192][64] f16
__device__ float  g_xp32[2 * M_ROWS * RANK];  // K-split partials, f32

// ---------------------------------------------------------------------------
// helpers
// ---------------------------------------------------------------------------
__device__ __forceinline__ void cp_async16(void* smem_dst, const void* gsrc) {
    unsigned s = (unsigned)__cvta_generic_to_shared(smem_dst);
    asm volatile("cp.async.cg.shared.global [%0], [%1], 16;\n" :: "r"(s), "l"(gsrc));
}
__device__ __forceinline__ void cp_async_commit() {
    asm volatile("cp.async.commit_group;\n");
}
template <int N>
__device__ __forceinline__ void cp_async_wait() {
    asm volatile("cp.async.wait_group %0;\n" :: "n"(N));
}

__device__ __forceinline__ void soft_threshold4(float4 w, float s,
                                                float& o0, float& o1, float& o2, float& o3) {
    float m0 = fabsf(w.x), m1 = fabsf(w.y), m2 = fabsf(w.z), m3 = fabsf(w.w);
    float lo01 = fminf(m0, m1), hi01 = fmaxf(m0, m1);
    float lo23 = fminf(m2, m3), hi23 = fmaxf(m2, m3);
    float t = fminf(fmaxf(lo01, lo23), fminf(hi01, hi23));  // 2nd-smallest
    o0 = copysignf(fmaxf(m0 - t, 0.0f), w.x) * s;
    o1 = copysignf(fmaxf(m1 - t, 0.0f), w.y) * s;
    o2 = copysignf(fmaxf(m2 - t, 0.0f), w.z) * s;
    o3 = copysignf(fmaxf(m3 - t, 0.0f), w.w) * s;
}

// ---------------------------------------------------------------------------
// Weight prep: threshold+scale -> g_win, g_wout
// ---------------------------------------------------------------------------
__global__ void prep_weights_kernel(const float* __restrict__ win,
                                    const float* __restrict__ wout,
                                    const float* __restrict__ scale_in,
                                    const float* __restrict__ scale_out) {
    const int NGI = RANK * IN_F / 4;    // 65536
    const int NGO = OUT_F * RANK / 4;   // 65536
    int idx = blockIdx.x * blockDim.x + threadIdx.x;
    if (idx < NGI) {
        float4 w = reinterpret_cast<const float4*>(win)[idx];
        float o0, o1, o2, o3;
        soft_threshold4(w, __ldg(scale_in), o0, o1, o2, o3);
        __half2* dst = reinterpret_cast<__half2*>(g_win) + idx * 2;
        dst[0] = __floats2half2_rn(o0, o1);
        dst[1] = __floats2half2_rn(o2, o3);
    } else if (idx < NGI + NGO) {
        int j = idx - NGI;
        float4 w = reinterpret_cast<const float4*>(wout)[j];
        float o0, o1, o2, o3;
        soft_threshold4(w, __ldg(scale_out), o0, o1, o2, o3);
        __half2* dst = reinterpret_cast<__half2*>(g_wout) + j * 2;
        dst[0] = __floats2half2_rn(o0, o1);
        dst[1] = __floats2half2_rn(o2, o3);
    }
}

// ---------------------------------------------------------------------------
// GEMM1 (K-split x2): xp32[ks][m,r] = sum_{k in half ks} f16(x[m,k])*g_win[r,k]
// BM=64, BK=64, grid (128, 2), 2 CTAs/SM, double-buffered, 2-deep prefetch.
// (round-15 exact — best measured; occ=2 is required, 3 spills)
// ---------------------------------------------------------------------------
#define G1_LDA 72   // half, padded

__global__ __launch_bounds__(256, 2)
void gemm1_kernel(const float* __restrict__ x) {
    extern __shared__ __half sm1[];
    __half* A0 = sm1;                   // [64][72]
    __half* A1 = sm1 + 64 * G1_LDA;
    __half* B0 = sm1 + 2 * 64 * G1_LDA;
    __half* B1 = sm1 + 3 * 64 * G1_LDA;

    const int tid  = threadIdx.x;
    const int warp = tid >> 5;
    const int wm   = warp & 3;   // 16 rows
    const int wn   = warp >> 2;  // 32 cols
    const int m0   = blockIdx.x * 64;
    const int ks   = blockIdx.y;
    const int k0   = ks * (IN_F / 2);

    wmma::fragment<wmma::accumulator, 16, 16, 16, float> acc[2];
    wmma::fill_fragment(acc[0], 0.0f);
    wmma::fill_fragment(acc[1], 0.0f);

    const int NK = (IN_F / 2) / 64;  // 32

    float4 xa0[4], xa1[4];
    int4   wb0[2], wb1[2];

    auto ldx = [&](float4* xa, int kt) {
        #pragma unroll
        for (int it = 0; it < 4; it++) {
            int i = tid + it * 256;
            int row = i >> 4, c4 = i & 15;
            xa[it] = __ldcs(reinterpret_cast<const float4*>(
                &x[(size_t)(m0 + row) * IN_F + k0 + kt * 64 + c4 * 4]));
        }
    };
    auto ldw = [&](int4* wb, int kt) {
        #pragma unroll
        for (int it = 0; it < 2; it++) {
            int i = tid + it * 256;
            int row = i >> 3, c8 = i & 7;
            wb[it] = *reinterpret_cast<const int4*>(
                &g_win[row * IN_F + k0 + kt * 64 + c8 * 8]);
        }
    };
    auto stage = [&](__half* A, __half* B, const float4* xa, const int4* wb) {
        #pragma unroll
        for (int it = 0; it < 4; it++) {
            int i = tid + it * 256;
            int row = i >> 4, c4 = i & 15;
            __half* p = &A[row * G1_LDA + c4 * 4];
            reinterpret_cast<__half2*>(p)[0] = __floats2half2_rn(xa[it].x, xa[it].y);
            reinterpret_cast<__half2*>(p)[1] = __floats2half2_rn(xa[it].z, xa[it].w);
        }
        #pragma unroll
        for (int it = 0; it < 2; it++) {
            int i = tid + it * 256;
            int row = i >> 3, c8 = i & 7;
            *reinterpret_cast<int4*>(&B[row * G1_LDA + c8 * 8]) = wb[it];
        }
    };
    auto mma = [&](const __half* A, const __half* B) {
        #pragma unroll
        for (int k4 = 0; k4 < 4; k4++) {
            wmma::fragment<wmma::matrix_a, 16, 16, 16, __half, wmma::row_major> a;
            wmma::load_matrix_sync(a, &A[(wm * 16) * G1_LDA + k4 * 16], G1_LDA);
            #pragma unroll
            for (int j = 0; j < 2; j++) {
                wmma::fragment<wmma::matrix_b, 16, 16, 16, __half, wmma::col_major> b;
                wmma::load_matrix_sync(b, &B[(wn * 32 + j * 16) * G1_LDA + k4 * 16], G1_LDA);
                wmma::mma_sync(acc[j], a, b, acc[j]);
            }
        }
    };

    ldx(xa0, 0); ldw(wb0, 0);
    ldx(xa1, 1); ldw(wb1, 1);

    for (int kt = 0; kt < NK; kt += 2) {
        stage(A0, B0, xa0, wb0);
        __syncthreads();
        if (kt + 2 < NK) { ldx(xa0, kt + 2); ldw(wb0, kt + 2); }
        mma(A0, B0);

        stage(A1, B1, xa1, wb1);
        __syncthreads();
        if (kt + 3 < NK) { ldx(xa1, kt + 3); ldw(wb1, kt + 3); }
        mma(A1, B1);
    }

    float* outp = g_xp32 + (size_t)ks * M_ROWS * RANK;
    #pragma unroll
    for (int j = 0; j < 2; j++)
        wmma::store_matrix_sync(&outp[(size_t)(m0 + wm * 16) * RANK + wn * 32 + j * 16],
                                acc[j], RANK, wmma::mem_row_major);
}

// ---------------------------------------------------------------------------
// Combine: g_xp[m][c] = f16(xp32[0][m][c] + xp32[1][m][c])  ([8192][64])
// float4-wide loads for MLP.
// ---------------------------------------------------------------------------
__global__ void combine_xp_kernel() {
    int i = blockIdx.x * blockDim.x + threadIdx.x;   // over 8192*16 float4
    if (i >= M_ROWS * (RANK / 4)) return;
    float4 a = __ldcg(reinterpret_cast<const float4*>(g_xp32) + i);
    float4 b = __ldcg(reinterpret_cast<const float4*>(g_xp32 + (size_t)M_ROWS * RANK) + i);
    __half2 h0 = __floats2half2_rn(a.x + b.x, a.y + b.y);
    __half2 h1 = __floats2half2_rn(a.z + b.z, a.w + b.w);
    reinterpret_cast<__half2*>(g_xp)[i * 2]     = h0;
    reinterpret_cast<__half2*>(g_xp)[i * 2 + 1] = h1;
}

// ---------------------------------------------------------------------------
// GEMM2: out[m,o] = (xp[m,:] . wout[o,:] + bias[o]) / 64   (K=64)
// BM=128, BN=128. Bias via single-row smem + ldm=0 broadcast fragment load.
// Direct store_matrix_sync epilogue. (round-14/15 exact — best measured)
// ---------------------------------------------------------------------------
#define G2_LD 72    // half, padded (K=64)

__global__ __launch_bounds__(256, 2)
void gemm2_kernel(const float* __restrict__ bias, float* __restrict__ out) {
    extern __shared__ __half sm2[];
    __half* Ps = sm2;                 // [128][72]  18432 B
    __half* Ws = sm2 + 128 * G2_LD;   // [128][72]  18432 B
    float* bias_row = reinterpret_cast<float*>(sm2 + 2 * 128 * G2_LD);  // [128] 512 B

    const int tid  = threadIdx.x;
    const int warp = tid >> 5;
    const int wm   = warp & 3;   // 32 rows
    const int wn   = warp >> 2;  // 64 cols
    const int m0   = blockIdx.x * 128;
    const int n0   = blockIdx.y * 128;

    #pragma unroll
    for (int it = 0; it < 4; it++) {
        int c = tid + it * 256;
        int row = c >> 3, off = c & 7;
        cp_async16(Ps + row * G2_LD + off * 8,
                   g_xp + (size_t)(m0 + row) * RANK + off * 8);
    }
    #pragma unroll
    for (int it = 0; it < 4; it++) {
        int c = tid + it * 256;
        int row = c >> 3, off = c & 7;
        cp_async16(Ws + row * G2_LD + off * 8,
                   g_wout + (size_t)(n0 + row) * RANK + off * 8);
    }
    cp_async_commit();

    if (tid < 128) bias_row[tid] = __ldg(&bias[n0 + tid]);

    cp_async_wait<0>();
    __syncthreads();

    wmma::fragment<wmma::accumulator, 16, 16, 16, float> acc[2][4];
    #pragma unroll
    for (int i = 0; i < 2; i++)
        #pragma unroll
        for (int j = 0; j < 4; j++) wmma::fill_fragment(acc[i][j], 0.0f);

    #pragma unroll
    for (int k4 = 0; k4 < 4; k4++) {   // K = 64
        wmma::fragment<wmma::matrix_a, 16, 16, 16, __half, wmma::row_major> a[2];
        #pragma unroll
        for (int i = 0; i < 2; i++)
            wmma::load_matrix_sync(a[i], &Ps[(wm * 32 + i * 16) * G2_LD + k4 * 16], G2_LD);
        #pragma unroll
        for (int j = 0; j < 4; j++) {
            wmma::fragment<wmma::matrix_b, 16, 16, 16, __half, wmma::col_major> b;
            wmma::load_matrix_sync(b, &Ws[(wn * 64 + j * 16) * G2_LD + k4 * 16], G2_LD);
            #pragma unroll
            for (int i = 0; i < 2; i++)
                wmma::mma_sync(acc[i][j], a[i], b, acc[i][j]);
        }
    }

    const float scaling = 1.0f / (float)RANK;
    #pragma unroll
    for (int i = 0; i < 2; i++)
        #pragma unroll
        for (int j = 0; j < 4; j++) {
            // ldm=0: every fragment row aliases the same 64B bias row;
            // value depends only on column -> layout-independent.
            wmma::fragment<wmma::accumulator, 16, 16, 16, float> bf;
            wmma::load_matrix_sync(bf, &bias_row[wn * 64 + j * 16], 0,
                                   wmma::mem_row_major);
            #pragma unroll
            for (int e = 0; e < acc[i][j].num_elements; e++)
                acc[i][j].x[e] = (acc[i][j].x[e] + bf.x[e]) * scaling;
            wmma::store_matrix_sync(
                &out[(size_t)(m0 + wm * 32 + i * 16) * OUT_F + n0 + wn * 64 + j * 16],
                acc[i][j], OUT_F, wmma::mem_row_major);
        }
}

// ---------------------------------------------------------------------------
// Launcher
// ---------------------------------------------------------------------------
extern "C" void kernel_launch(void* const* d_in, const int* in_sizes, int n_in,
                              void* d_out, int out_size) {
    const float* x         = (const float*)d_in[0];
    const float* weight_in = (const float*)d_in[1];
    const float* weight_out= (const float*)d_in[2];
    const float* bias      = (const float*)d_in[3];
    const float* scale_in  = (const float*)d_in[4];
    const float* scale_out = (const float*)d_in[5];
    float* out = (float*)d_out;

    const int M = in_sizes[0] / IN_F;  // 8192

    {
        int total = RANK * IN_F / 4 + OUT_F * RANK / 4;   // 131072
        prep_weights_kernel<<<(total + 255) / 256, 256>>>(
            weight_in, weight_out, scale_in, scale_out);
    }
    {
        size_t smem = 4 * (size_t)64 * G1_LDA * sizeof(__half);  // 36864
        dim3 grid(M / 64, 2);
        gemm1_kernel<<<grid, 256, smem>>>(x);
    }
    {
        int total = M_ROWS * (RANK / 4);  // 131072
        combine_xp_kernel<<<(total + 255) / 256, 256>>>();
    }
    {
        size_t smem = 2 * (size_t)128 * G2_LD * sizeof(__half) + 512;  // 37376
        dim3 grid(M / 128, OUT_F / 128);
        gemm2_kernel<<<grid, 256, smem>>>(bias, out);
    }
}